// round 8
// baseline (speedup 1.0000x reference)
#include <cuda_runtime.h>
#include <cuda_bf16.h>

// Problem constants
#define B_  16
#define R_  64
#define S_  128
#define M_  64
#define L_  128
#define E_  4032            // R*R - R

// Output layout (float elements), 5 concatenated outputs:
#define OFF_INC_ADD  0ull
#define OFF_INC_GAIN 131072ull
#define OFF_MEAN     262144ull
#define OFF_LOG      4456448ull
#define OFF_MSG      8650752ull

// Shared layout (floats)
#define XS_OFF    0            // xs[b][s], stride 132:      16*132 = 2112
#define WU_OFF    2112         // per-warp weight union: 8 * 2176 = 17408
#define SMEAN_OFF 19520        // smean[b][m], stride 68:    16*68 = 1088
#define SLOG_OFF  20608        // slog[b][m],  stride 68:            1088
#define SADD_OFF  21696        // sadd[b][l],  stride 132:           2112
#define SGAIN_OFF 23808        // sgain[b][l], stride 132:           2112
#define SMEM_FLOATS 25920      // 103680 bytes
#define XSS  132               // xs row stride
#define W2S  132               // phase-2 weight row stride (128+4)
#define W3S  68                // phase-3 weight row stride (64+4)
#define SMS  68                // smean/slog row stride
#define SAS  132               // sadd/sgain row stride
#define WUSZ 2176              // per-warp weight union size (floats)

typedef unsigned long long ull;

__device__ __forceinline__ ull fma2(ull a, ull b, ull c) {
    ull d;
    asm("fma.rn.f32x2 %0, %1, %2, %3;" : "=l"(d) : "l"(a), "l"(b), "l"(c));
    return d;
}
__device__ __forceinline__ void unpk(ull v, float& lo, float& hi) {
    asm("mov.b64 {%0, %1}, %2;" : "=f"(lo), "=f"(hi) : "l"(v));
}
__device__ __forceinline__ void red_add_v4(float* p, float4 v) {
    asm volatile("red.global.add.v4.f32 [%0], {%1, %2, %3, %4};"
                 :: "l"(p), "f"(v.x), "f"(v.y), "f"(v.z), "f"(v.w) : "memory");
}
__device__ __forceinline__ void cpa16(float* dst_smem, const float* src) {
    unsigned sa = (unsigned)__cvta_generic_to_shared(dst_smem);
    asm volatile("cp.async.cg.shared.global [%0], [%1], 16;" :: "r"(sa), "l"(src));
}
__device__ __forceinline__ void cp_commit() { asm volatile("cp.async.commit_group;"); }
__device__ __forceinline__ void cp_wait1()  { asm volatile("cp.async.wait_group 1;" ::: "memory"); }
__device__ __forceinline__ void cp_wait0()  { asm volatile("cp.async.wait_group 0;" ::: "memory"); }
__device__ __forceinline__ void bar_sync(int id, int cnt) {
    asm volatile("bar.sync %0, %1;" :: "r"(id), "r"(cnt) : "memory");
}
__device__ __forceinline__ void bar_arrive(int id, int cnt) {
    asm volatile("bar.arrive %0, %1;" :: "r"(id), "r"(cnt) : "memory");
}

// ---------------- init: zero inc regions + scat diagonals ----------------
__global__ void init_kernel(float* __restrict__ out) {
    int idx = blockIdx.x * blockDim.x + threadIdx.x;
    if (idx < 2 * B_ * R_ * L_) out[idx] = 0.0f;
    if (idx < 3 * B_ * R_ * M_) {
        int o  = idx / (B_ * R_ * M_);
        int r2 = idx % (B_ * R_ * M_);
        int b  = r2 / (R_ * M_);
        int rm = r2 % (R_ * M_);
        int r  = rm / M_;
        int m  = rm % M_;
        ull base = (o == 0) ? OFF_MEAN : ((o == 1) ? OFF_LOG : OFF_MSG);
        out[base + ((((ull)b * R_ + r) * R_ + r) * M_ + m)] = 0.0f;
    }
}

// ---------------- main: one block per edge, warp-autonomous pipelines ----
__global__ __launch_bounds__(256, 2) void edge_kernel(
    const float* __restrict__ source,
    const float* __restrict__ mean_w,
    const float* __restrict__ mean_b,
    const float* __restrict__ logstd_w,
    const float* __restrict__ logstd_b,
    const float* __restrict__ add_w,
    const float* __restrict__ gain_w,
    float* __restrict__ out)
{
    extern __shared__ float sm[];
    float* xs    = sm + XS_OFF;      // [b][s] stride 132
    float* smean = sm + SMEAN_OFF;   // [b][m] stride 68
    float* slog  = sm + SLOG_OFF;
    float* sadd  = sm + SADD_OFF;    // [b][l] stride 132
    float* sgain = sm + SGAIN_OFF;

    const int e = blockIdx.x;
    const int s_idx = e / (R_ - 1);
    const int rem   = e % (R_ - 1);
    const int t_idx = rem + (rem >= s_idx ? 1 : 0);
    const int tid  = threadIdx.x;
    const int w    = tid >> 5;           // warp 0..7
    const int lane = tid & 31;
    const bool isA = (w < 4);
    const int  wp  = w & 3;              // warp within sub
    const int  u   = tid & 127;          // thread within sub
    float* WU = sm + WU_OFF + w * WUSZ;  // this warp's weight buffer

    // ================= staging: xs (block-shared, g0) + own w2 rows (g1) ====
    #pragma unroll
    for (int k = 0; k < 2; k++) {
        int i = tid + k * 256;
        int b = i >> 5, c = i & 31;
        cpa16(xs + b * XSS + c * 4,
              source + (ull)b * (R_ * S_) + (ull)s_idx * S_ + c * 4);
    }
    cp_commit();                                  // g0 = xs share
    {
        const float* w2src = isA ? mean_w : logstd_w;
        const int R0 = wp * 16;
        #pragma unroll
        for (int k = 0; k < 16; k++) {
            cpa16(WU + k * W2S + lane * 4,
                  w2src + ((ull)e * M_ + R0 + k) * S_ + lane * 4);
        }
    }
    cp_commit();                                  // g1 = own 16 weight rows

    // bias prefetch (2 scalars per lane)
    const int pr = lane >> 2;                     // 0..7  row-pair
    const int bq = lane & 3;                      // 0..3  batch-phase
    const int R0 = wp * 16;
    const int m0 = R0 + 2 * pr;                   // sub-local rows m0, m0+1
    const float* bsrc = isA ? mean_b : logstd_b;
    const float bias0 = bsrc[(ull)e * M_ + m0];
    const float bias1 = bsrc[(ull)e * M_ + m0 + 1];

    cp_wait1();                                   // xs arrived (own share)
    __syncthreads();                              // xs arrived (all shares)
    cp_wait0();                                   // own weights arrived

    // ================= phase 2: 2 rows x 4 batches per lane =================
    {
        const float* wr0 = WU + (2 * pr) * W2S;
        const float* wr1 = WU + (2 * pr + 1) * W2S;
        ull acc[2][4];
        #pragma unroll
        for (int r = 0; r < 2; r++)
            #pragma unroll
            for (int i = 0; i < 4; i++) acc[r][i] = 0ull;

        #pragma unroll 4
        for (int c = 0; c < 16; c++) {            // 8 s per chunk
            ulonglong2 wa0 = *reinterpret_cast<const ulonglong2*>(wr0 + 8 * c);
            ulonglong2 wb0 = *reinterpret_cast<const ulonglong2*>(wr0 + 8 * c + 4);
            ulonglong2 wa1 = *reinterpret_cast<const ulonglong2*>(wr1 + 8 * c);
            ulonglong2 wb1 = *reinterpret_cast<const ulonglong2*>(wr1 + 8 * c + 4);
            #pragma unroll
            for (int i = 0; i < 4; i++) {
                const int b = 4 * i + bq;
                const float* xr = xs + b * XSS + 8 * c;
                ulonglong2 xa = *reinterpret_cast<const ulonglong2*>(xr);
                ulonglong2 xb = *reinterpret_cast<const ulonglong2*>(xr + 4);
                acc[0][i] = fma2(xa.x, wa0.x, acc[0][i]);
                acc[0][i] = fma2(xa.y, wa0.y, acc[0][i]);
                acc[0][i] = fma2(xb.x, wb0.x, acc[0][i]);
                acc[0][i] = fma2(xb.y, wb0.y, acc[0][i]);
                acc[1][i] = fma2(xa.x, wa1.x, acc[1][i]);
                acc[1][i] = fma2(xa.y, wa1.y, acc[1][i]);
                acc[1][i] = fma2(xb.x, wb1.x, acc[1][i]);
                acc[1][i] = fma2(xb.y, wb1.y, acc[1][i]);
            }
        }

        float* sres2 = isA ? smean : slog;
        #pragma unroll
        for (int r = 0; r < 2; r++) {
            const int m = m0 + r;
            const float bias = r ? bias1 : bias0;
            #pragma unroll
            for (int i = 0; i < 4; i++) {
                const int b = 4 * i + bq;
                float lo, hi;
                unpk(acc[r][i], lo, hi);
                sres2[b * SMS + m] = lo + hi + bias;
            }
        }
    }

    // ---- sub barrier: phase-2 results visible within sub; publish smean ----
    if (isA) { bar_sync(1, 128); bar_arrive(3, 256); }
    else     { bar_sync(2, 128); }

    // ================= staging: own w3 rows (g0) ============================
    {
        const float* w3src = isA ? add_w : gain_w;
        const int R3 = wp * 32;
        #pragma unroll
        for (int k = 0; k < 16; k++) {
            int c   = lane + 32 * k;
            int row = c >> 4;
            int col = c & 15;
            cpa16(WU + row * W3S + col * 4,
                  w3src + ((ull)e * L_ + R3 + row) * M_ + col * 4);
        }
    }
    cp_commit();

    // ---- store pass (overlaps w3 staging): mean/msg from smean, log from slog
    {
        const ull cellb = (ull)(s_idx * R_ + t_idx) * M_;
        #pragma unroll
        for (int k = 0; k < 2; k++) {
            int chunk = u + 128 * k;
            int b  = chunk >> 4;
            int mq = chunk & 15;
            ull a = (ull)b * (R_ * R_ * M_) + cellb + mq * 4;
            if (isA) {
                float4 v = *reinterpret_cast<const float4*>(smean + b * SMS + mq * 4);
                *reinterpret_cast<float4*>(out + OFF_MEAN + a) = v;
                *reinterpret_cast<float4*>(out + OFF_MSG  + a) = v;
            } else {
                float4 v = *reinterpret_cast<const float4*>(slog + b * SMS + mq * 4);
                *reinterpret_cast<float4*>(out + OFF_LOG + a) = v;
            }
        }
    }

    cp_wait0();                                   // own w3 rows arrived
    if (!isA) bar_sync(3, 256);                   // wait smean from SubA

    // ================= phase 3: 2 rows x 8 batches per lane =================
    {
        const int pr3 = lane >> 1;                // 0..15 row-pair
        const int bq3 = lane & 1;                 // 0..1  batch-phase
        const int R3  = wp * 32;
        const int l0  = R3 + 2 * pr3;

        const float* wr0 = WU + (2 * pr3) * W3S;
        const float* wr1 = WU + (2 * pr3 + 1) * W3S;

        ull acc[2][8];
        #pragma unroll
        for (int r = 0; r < 2; r++)
            #pragma unroll
            for (int i = 0; i < 8; i++) acc[r][i] = 0ull;

        #pragma unroll 2
        for (int c = 0; c < 8; c++) {             // 8 m per chunk
            ulonglong2 wa0 = *reinterpret_cast<const ulonglong2*>(wr0 + 8 * c);
            ulonglong2 wb0 = *reinterpret_cast<const ulonglong2*>(wr0 + 8 * c + 4);
            ulonglong2 wa1 = *reinterpret_cast<const ulonglong2*>(wr1 + 8 * c);
            ulonglong2 wb1 = *reinterpret_cast<const ulonglong2*>(wr1 + 8 * c + 4);
            #pragma unroll
            for (int i = 0; i < 8; i++) {
                const int b = 2 * i + bq3;
                const float* mr = smean + b * SMS + 8 * c;
                ulonglong2 xa = *reinterpret_cast<const ulonglong2*>(mr);
                ulonglong2 xb = *reinterpret_cast<const ulonglong2*>(mr + 4);
                acc[0][i] = fma2(xa.x, wa0.x, acc[0][i]);
                acc[0][i] = fma2(xa.y, wa0.y, acc[0][i]);
                acc[0][i] = fma2(xb.x, wb0.x, acc[0][i]);
                acc[0][i] = fma2(xb.y, wb0.y, acc[0][i]);
                acc[1][i] = fma2(xa.x, wa1.x, acc[1][i]);
                acc[1][i] = fma2(xa.y, wa1.y, acc[1][i]);
                acc[1][i] = fma2(xb.x, wb1.x, acc[1][i]);
                acc[1][i] = fma2(xb.y, wb1.y, acc[1][i]);
            }
        }

        float* sres = isA ? sadd : sgain;
        #pragma unroll
        for (int r = 0; r < 2; r++) {
            const int l = l0 + r;
            #pragma unroll
            for (int i = 0; i < 8; i++) {
                const int b = 2 * i + bq3;
                float lo, hi;
                unpk(acc[r][i], lo, hi);
                sres[b * SAS + l] = lo + hi;
            }
        }
    }
    if (isA) bar_sync(1, 128);
    else     bar_sync(2, 128);

    // ================= phase 4: vectorized scatter-add ======================
    {
        float* sres = isA ? sadd : sgain;
        const ull offI = isA ? OFF_INC_ADD : OFF_INC_GAIN;
        #pragma unroll
        for (int k = 0; k < 4; k++) {
            int i = u + 128 * k;
            int b = i >> 5;
            int q = i & 31;
            float4 v = *reinterpret_cast<const float4*>(sres + b * SAS + q * 4);
            float* dst = out + offI + (ull)(b * R_ + t_idx) * L_ + q * 4;
            red_add_v4(dst, v);
        }
    }
}

extern "C" void kernel_launch(void* const* d_in, const int* in_sizes, int n_in,
                              void* d_out, int out_size) {
    const float* source   = (const float*)d_in[0];
    const float* mean_w   = (const float*)d_in[1];
    const float* mean_b   = (const float*)d_in[2];
    const float* logstd_w = (const float*)d_in[3];
    const float* logstd_b = (const float*)d_in[4];
    const float* add_w    = (const float*)d_in[5];
    const float* gain_w   = (const float*)d_in[6];
    float* out = (float*)d_out;

    cudaFuncSetAttribute(edge_kernel, cudaFuncAttributeMaxDynamicSharedMemorySize,
                         SMEM_FLOATS * 4);

    init_kernel<<<(2 * B_ * R_ * L_ + 255) / 256, 256>>>(out);
    edge_kernel<<<E_, 256, SMEM_FLOATS * 4>>>(source, mean_w, mean_b,
                                              logstd_w, logstd_b,
                                              add_w, gain_w, out);
}